// round 4
// baseline (speedup 1.0000x reference)
#include <cuda_runtime.h>
#include <math.h>

#define BB 65536
#define HH 256
#define EE 64
#define DD 2
#define PP 12
#define G4 1024          // 4*H
#define KTOT 320         // E + H
#define TM 64            // rows per CTA
#define KT 32            // k-tile (gates)
#define KTH 64           // k-tile (heads)
#define NT 256           // threads per CTA

typedef unsigned long long u64;

// -------- scratch (allocation-free: __device__ globals) --------
__device__ float g_Wt[KTOT * G4];      // packed transposed [k][g*256 + j]
__device__ float g_WheadT[HH * 128];   // [k][0..63]=W_sp1^T, [64..127]=W_un1^T

__global__ void prep_kernel(const float* __restrict__ W_ih,
                            const float* __restrict__ W_hh,
                            const float* __restrict__ W_sp1,
                            const float* __restrict__ W_un1) {
    int idx = blockIdx.x * blockDim.x + threadIdx.x;
    if (idx < KTOT * G4) {
        int k = idx >> 10, j = idx & 1023;
        g_Wt[idx] = (k < EE) ? W_ih[j * EE + k] : W_hh[j * HH + (k - EE)];
    } else {
        int r = idx - KTOT * G4;
        if (r < HH * 128) {
            int k = r >> 7, o = r & 127;
            g_WheadT[r] = (o < 64) ? W_sp1[o * HH + k] : W_un1[(o - 64) * HH + k];
        }
    }
}

__device__ __forceinline__ float sigf(float x) { return 1.f / (1.f + expf(-x)); }
__device__ __forceinline__ float softplusf(float x) {
    return fmaxf(x, 0.f) + log1pf(expf(-fabsf(x)));
}

__device__ __forceinline__ u64 pack2(float lo, float hi) {
    u64 r;
    asm("mov.b64 %0, {%1, %2};" : "=l"(r)
        : "r"(__float_as_uint(lo)), "r"(__float_as_uint(hi)));
    return r;
}
__device__ __forceinline__ void unpack2(u64 v, float& lo, float& hi) {
    unsigned int a, b;
    asm("mov.b64 {%0, %1}, %2;" : "=r"(a), "=r"(b) : "l"(v));
    lo = __uint_as_float(a); hi = __uint_as_float(b);
}
#define FMA2(d, a, b) asm("fma.rn.f32x2 %0, %1, %2, %0;" : "+l"(d) : "l"(a), "l"(b))

// -------- main persistent-state kernel --------
__global__ void __launch_bounds__(NT, 1)
lstm_kernel(const float* __restrict__ enc_h, const float* __restrict__ enc_c,
            const float* __restrict__ last_pos,
            const float* __restrict__ W_embed, const float* __restrict__ b_embed,
            const float* __restrict__ b_ih, const float* __restrict__ b_hh,
            const float* __restrict__ W_pos, const float* __restrict__ b_pos,
            const float* __restrict__ b_sp1, const float* __restrict__ W_sp2,
            const float* __restrict__ b_sp2,
            const float* __restrict__ b_un1, const float* __restrict__ W_un2,
            const float* __restrict__ b_un2,
            float* __restrict__ out)
{
    extern __shared__ float sm[];
    float* hs0   = sm;                    // [TM][HH] 16384
    float* hs1   = hs0 + TM * HH;         // [TM][HH] 16384
    float* embs  = hs1 + TM * HH;         // [TM][EE]  4096
    float* wt    = embs + TM * EE;        // 8192 (KT x 256 gates / KTH x 128 heads)
    float* bg    = wt + 8192;             // [1024]
    float* wposI = bg + G4;               // [256][2] interleaved  512
    float* s_bsp1 = wposI + 512;          // 64
    float* s_bun1 = s_bsp1 + 64;          // 64
    float* s_wsp2 = s_bun1 + 64;          // 64
    float* s_wun2 = s_wsp2 + 64;          // [2][64] 128
    float* s_wemb = s_wun2 + 128;         // [E][D]  128
    float* s_bemb = s_wemb + 128;         // 64
    float* s_misc = s_bemb + 64;          // 8
    float* ps     = s_misc + 8;           // [TM][2] 128

    const int tid  = threadIdx.x;
    const int lane = tid & 31;
    const int w    = tid >> 5;
    const int row0 = blockIdx.x * TM;
    const int myrow = w * 8;              // warp owns 8 rows

    // ---- init ----
    for (int i = tid; i < TM * HH; i += NT) hs0[i] = enc_h[row0 * HH + i];
    for (int i = tid; i < TM * DD; i += NT) ps[i] = last_pos[row0 * DD + i];
    for (int i = tid; i < G4; i += NT) bg[i] = b_ih[i] + b_hh[i];
    if (tid < 256) { wposI[2 * tid] = W_pos[tid]; wposI[2 * tid + 1] = W_pos[HH + tid]; }
    for (int i = tid; i < 128; i += NT) { s_wun2[i] = W_un2[i]; s_wemb[i] = W_embed[i]; }
    if (tid < 64) {
        s_bsp1[tid] = b_sp1[tid]; s_bun1[tid] = b_un1[tid];
        s_wsp2[tid] = W_sp2[tid]; s_bemb[tid] = b_embed[tid];
    }
    if (tid == 0) {
        s_misc[0] = b_pos[0]; s_misc[1] = b_pos[1];
        s_misc[2] = b_sp2[0]; s_misc[3] = b_un2[0]; s_misc[4] = b_un2[1];
    }

    // c-state in registers: c2[hc*8+r] = pair (j=hc*64+2*lane, +1) of row myrow+r
    u64 c2[32];
    #pragma unroll
    for (int hc = 0; hc < 4; hc++)
        #pragma unroll
        for (int r = 0; r < 8; r++) {
            float2 v = *(const float2*)&enc_c[(size_t)(row0 + myrow + r) * HH + hc * 64 + 2 * lane];
            c2[hc * 8 + r] = pack2(v.x, v.y);
        }
    __syncthreads();

    float* out_pred = out;
    float* out_sp   = out + (size_t)BB * PP * 2;
    float* out_un   = out + (size_t)BB * PP * 3;

    for (int step = 0; step < PP; step++) {
        float* hsOld = (step & 1) ? hs1 : hs0;
        float* hsNew = (step & 1) ? hs0 : hs1;

        // ---- 1. emb (per-warp: own 8 rows only) ----
        for (int i = lane; i < 8 * EE; i += 32) {
            int r = i >> 6, e = i & 63;
            int row = myrow + r;
            float v = fmaf(ps[row * 2], s_wemb[e * 2],
                      fmaf(ps[row * 2 + 1], s_wemb[e * 2 + 1], s_bemb[e]));
            embs[row * EE + e] = fmaxf(v, 0.f);
        }
        __syncwarp();

        // ---- 2. gates GEMM (FFMA2) + fused LSTM cell, 4 output chunks ----
        #pragma unroll 1
        for (int hc = 0; hc < 4; hc++) {
            u64 acc2[32];  // [gate 4][row 8]
            #pragma unroll
            for (int i = 0; i < 32; i++) acc2[i] = 0ULL;

            for (int kt = 0; kt < KTOT; kt += KT) {
                __syncthreads();
                #pragma unroll
                for (int it = 0; it < 8; it++) {          // KT*256/4/NT = 8
                    int fi  = it * NT + tid;
                    int k   = fi >> 6;
                    int jl4 = fi & 63;
                    int g   = jl4 >> 4;
                    int jj  = (jl4 & 15) * 4;
                    *(float4*)&wt[k * 256 + jl4 * 4] =
                        *(const float4*)&g_Wt[(size_t)(kt + k) * G4 + g * 256 + hc * 64 + jj];
                }
                __syncthreads();

                const float* Abase = (kt < EE) ? (embs + kt) : (hsOld + (kt - EE));
                const int astr     = (kt < EE) ? EE : HH;

                for (int k4 = 0; k4 < KT; k4 += 4) {
                    float4 a[8];
                    #pragma unroll
                    for (int r = 0; r < 8; r++)
                        a[r] = *(const float4*)&Abase[(myrow + r) * astr + k4];
                    #pragma unroll
                    for (int kk = 0; kk < 4; kk++) {
                        const float* wr = &wt[(k4 + kk) * 256 + 2 * lane];
                        u64 w0 = *(const u64*)&wr[0];
                        u64 w1 = *(const u64*)&wr[64];
                        u64 w2 = *(const u64*)&wr[128];
                        u64 w3 = *(const u64*)&wr[192];
                        #pragma unroll
                        for (int r = 0; r < 8; r++) {
                            float av = (kk == 0) ? a[r].x : (kk == 1) ? a[r].y
                                     : (kk == 2) ? a[r].z : a[r].w;
                            u64 av2 = pack2(av, av);
                            FMA2(acc2[r],      av2, w0);
                            FMA2(acc2[8 + r],  av2, w1);
                            FMA2(acc2[16 + r], av2, w2);
                            FMA2(acc2[24 + r], av2, w3);
                        }
                    }
                }
            }
            // fused LSTM cell update; writes h straight into hsNew (own rows)
            int jb = hc * 64 + 2 * lane;
            float2 bi = *(const float2*)&bg[jb];
            float2 bf = *(const float2*)&bg[256 + jb];
            float2 bgt = *(const float2*)&bg[512 + jb];
            float2 bo = *(const float2*)&bg[768 + jb];
            #pragma unroll
            for (int r = 0; r < 8; r++) {
                float i0, i1, f0, f1, g0, g1, o0, o1, co0, co1;
                unpack2(acc2[r],      i0, i1);
                unpack2(acc2[8 + r],  f0, f1);
                unpack2(acc2[16 + r], g0, g1);
                unpack2(acc2[24 + r], o0, o1);
                unpack2(c2[hc * 8 + r], co0, co1);
                float cn0 = sigf(f0 + bf.x) * co0 + sigf(i0 + bi.x) * tanhf(g0 + bgt.x);
                float cn1 = sigf(f1 + bf.y) * co1 + sigf(i1 + bi.y) * tanhf(g1 + bgt.y);
                c2[hc * 8 + r] = pack2(cn0, cn1);
                float h0 = sigf(o0 + bo.x) * tanhf(cn0);
                float h1 = sigf(o1 + bo.y) * tanhf(cn1);
                *(float2*)&hsNew[(myrow + r) * HH + jb] = make_float2(h0, h1);
            }
        }

        // ---- 3. heads (packed pairs; reads hsNew, own rows only) ----
        u64 t2[8], u2[8], p2[8];
        #pragma unroll
        for (int r = 0; r < 8; r++) { t2[r] = 0ULL; u2[r] = 0ULL; p2[r] = 0ULL; }

        for (int kt = 0; kt < HH; kt += KTH) {
            __syncthreads();
            #pragma unroll
            for (int it = 0; it < 8; it++) {              // KTH*128/4/NT = 8
                int fi  = it * NT + tid;
                int k   = fi >> 5;
                int jl4 = fi & 31;
                *(float4*)&wt[k * 128 + jl4 * 4] =
                    *(const float4*)&g_WheadT[(kt + k) * 128 + jl4 * 4];
            }
            __syncthreads();
            for (int k = 0; k < KTH; k++) {
                const float* wr = &wt[k * 128];
                u64 wsp = *(const u64*)&wr[2 * lane];
                u64 wun = *(const u64*)&wr[64 + 2 * lane];
                u64 wpp = *(const u64*)&wposI[(kt + k) * 2];
                #pragma unroll
                for (int r = 0; r < 8; r++) {
                    float hv = hsNew[(myrow + r) * HH + kt + k];
                    u64 hv2 = pack2(hv, hv);
                    FMA2(t2[r], hv2, wsp);
                    FMA2(u2[r], hv2, wun);
                    FMA2(p2[r], hv2, wpp);
                }
            }
        }

        float bspa = s_bsp1[2 * lane], bspb = s_bsp1[2 * lane + 1];
        float buna = s_bun1[2 * lane], bunb = s_bun1[2 * lane + 1];
        float wspa = s_wsp2[2 * lane], wspb = s_wsp2[2 * lane + 1];
        float wu0a = s_wun2[2 * lane],      wu0b = s_wun2[2 * lane + 1];
        float wu1a = s_wun2[64 + 2 * lane], wu1b = s_wun2[64 + 2 * lane + 1];

        #pragma unroll
        for (int r = 0; r < 8; r++) {
            float ta, tb, ua, ub, pr0, pr1;
            unpack2(t2[r], ta, tb);
            unpack2(u2[r], ua, ub);
            unpack2(p2[r], pr0, pr1);
            ta = fmaxf(ta + bspa, 0.f); tb = fmaxf(tb + bspb, 0.f);
            ua = fmaxf(ua + buna, 0.f); ub = fmaxf(ub + bunb, 0.f);
            float spv = ta * wspa + tb * wspb;
            float un0 = ua * wu0a + ub * wu0b;
            float un1 = ua * wu1a + ub * wu1b;
            #pragma unroll
            for (int off = 16; off > 0; off >>= 1) {
                spv += __shfl_xor_sync(0xffffffffu, spv, off);
                un0 += __shfl_xor_sync(0xffffffffu, un0, off);
                un1 += __shfl_xor_sync(0xffffffffu, un1, off);
            }
            if (lane == 0) {
                int row = myrow + r;
                int b   = row0 + row;
                float p0 = ps[row * 2]     + pr0 + s_misc[0];
                float p1 = ps[row * 2 + 1] + pr1 + s_misc[1];
                size_t base = (size_t)b * PP + step;
                out_pred[base * 2]     = p0;
                out_pred[base * 2 + 1] = p1;
                out_sp[base]           = softplusf(spv + s_misc[2]);
                out_un[base * 2]       = expf(un0 + s_misc[3]);
                out_un[base * 2 + 1]   = expf(un1 + s_misc[4]);
                ps[row * 2] = p0; ps[row * 2 + 1] = p1;
            }
        }
        __syncwarp();
    }
}

extern "C" void kernel_launch(void* const* d_in, const int* in_sizes, int n_in,
                              void* d_out, int out_size) {
    (void)in_sizes; (void)n_in; (void)out_size;
    const float* enc_h    = (const float*)d_in[0];
    const float* enc_c    = (const float*)d_in[1];
    const float* last_pos = (const float*)d_in[2];
    const float* W_embed  = (const float*)d_in[3];
    const float* b_embed  = (const float*)d_in[4];
    const float* W_ih     = (const float*)d_in[5];
    const float* W_hh     = (const float*)d_in[6];
    const float* b_ih     = (const float*)d_in[7];
    const float* b_hh     = (const float*)d_in[8];
    const float* W_pos    = (const float*)d_in[9];
    const float* b_pos    = (const float*)d_in[10];
    const float* W_sp1    = (const float*)d_in[11];
    const float* b_sp1    = (const float*)d_in[12];
    const float* W_sp2    = (const float*)d_in[13];
    const float* b_sp2    = (const float*)d_in[14];
    const float* W_un1    = (const float*)d_in[15];
    const float* b_un1    = (const float*)d_in[16];
    const float* W_un2    = (const float*)d_in[17];
    const float* b_un2    = (const float*)d_in[18];

    int prep_total = KTOT * G4 + HH * 128;
    prep_kernel<<<(prep_total + NT - 1) / NT, NT>>>(W_ih, W_hh, W_sp1, W_un1);

    const size_t smem = 47240 * sizeof(float);  // ~189 KB
    cudaFuncSetAttribute(lstm_kernel, cudaFuncAttributeMaxDynamicSharedMemorySize, (int)smem);
    lstm_kernel<<<BB / TM, NT, smem>>>(enc_h, enc_c, last_pos, W_embed, b_embed,
                                       b_ih, b_hh, W_pos, b_pos, b_sp1, W_sp2, b_sp2,
                                       b_un1, W_un2, b_un2, (float*)d_out);
}

// round 5
// speedup vs baseline: 1.0556x; 1.0556x over previous
#include <cuda_runtime.h>
#include <math.h>

#define BB 65536
#define HH 256
#define EE 64
#define DD 2
#define PP 12
#define G4 1024          // 4*H
#define KTOT 320         // E + H
#define TM 64            // rows per CTA
#define KT 32            // k-tile (gates)
#define KTH 64           // k-tile (heads)
#define NT 256           // threads per CTA

typedef unsigned long long u64;

// -------- scratch (allocation-free: __device__ globals) --------
__device__ float g_Wt[KTOT * G4];      // packed transposed [k][g*256 + j]
__device__ float g_WheadT[HH * 128];   // [k][0..63]=W_sp1^T, [64..127]=W_un1^T

__global__ void prep_kernel(const float* __restrict__ W_ih,
                            const float* __restrict__ W_hh,
                            const float* __restrict__ W_sp1,
                            const float* __restrict__ W_un1) {
    int idx = blockIdx.x * blockDim.x + threadIdx.x;
    if (idx < KTOT * G4) {
        int k = idx >> 10, j = idx & 1023;
        g_Wt[idx] = (k < EE) ? W_ih[j * EE + k] : W_hh[j * HH + (k - EE)];
    } else {
        int r = idx - KTOT * G4;
        if (r < HH * 128) {
            int k = r >> 7, o = r & 127;
            g_WheadT[r] = (o < 64) ? W_sp1[o * HH + k] : W_un1[(o - 64) * HH + k];
        }
    }
}

__device__ __forceinline__ float sigf(float x) { return 1.f / (1.f + expf(-x)); }
__device__ __forceinline__ float softplusf(float x) {
    return fmaxf(x, 0.f) + log1pf(expf(-fabsf(x)));
}

__device__ __forceinline__ u64 pack2(float lo, float hi) {
    u64 r;
    asm("mov.b64 %0, {%1, %2};" : "=l"(r)
        : "r"(__float_as_uint(lo)), "r"(__float_as_uint(hi)));
    return r;
}
__device__ __forceinline__ void unpack2(u64 v, float& lo, float& hi) {
    unsigned int a, b;
    asm("mov.b64 {%0, %1}, %2;" : "=r"(a), "=r"(b) : "l"(v));
    lo = __uint_as_float(a); hi = __uint_as_float(b);
}
#define FMA2(d, a, b) asm("fma.rn.f32x2 %0, %1, %2, %0;" : "+l"(d) : "l"(a), "l"(b))

// -------- main persistent-state kernel --------
__global__ void __launch_bounds__(NT, 1)
lstm_kernel(const float* __restrict__ enc_h, const float* __restrict__ enc_c,
            const float* __restrict__ last_pos,
            const float* __restrict__ W_embed, const float* __restrict__ b_embed,
            const float* __restrict__ b_ih, const float* __restrict__ b_hh,
            const float* __restrict__ W_pos, const float* __restrict__ b_pos,
            const float* __restrict__ b_sp1, const float* __restrict__ W_sp2,
            const float* __restrict__ b_sp2,
            const float* __restrict__ b_un1, const float* __restrict__ W_un2,
            const float* __restrict__ b_un2,
            float* __restrict__ out)
{
    extern __shared__ float sm[];
    float* hs0   = sm;                    // [TM][HH] 16384
    float* hs1   = hs0 + TM * HH;         // [TM][HH] 16384
    float* embs  = hs1 + TM * HH;         // [TM][EE]  4096
    float* wt    = embs + TM * EE;        // 8192 (KT x 256 gates / KTH x 128 heads)
    float* bg    = wt + 8192;             // [1024]
    float* wposI = bg + G4;               // [256][2] interleaved  512
    float* s_bsp1 = wposI + 512;          // 64
    float* s_bun1 = s_bsp1 + 64;          // 64
    float* s_wsp2 = s_bun1 + 64;          // 64
    float* s_wun2 = s_wsp2 + 64;          // [2][64] 128
    float* s_wemb = s_wun2 + 128;         // [E][D]  128
    float* s_bemb = s_wemb + 128;         // 64
    float* s_misc = s_bemb + 64;          // 8
    float* ps     = s_misc + 8;           // [TM][2] 128

    const int tid  = threadIdx.x;
    const int lane = tid & 31;
    const int w    = tid >> 5;
    const int row0 = blockIdx.x * TM;
    const int myrow = w * 8;              // warp owns 8 rows

    // ---- init ----
    for (int i = tid; i < TM * HH; i += NT) hs0[i] = enc_h[row0 * HH + i];
    for (int i = tid; i < TM * DD; i += NT) ps[i] = last_pos[row0 * DD + i];
    for (int i = tid; i < G4; i += NT) bg[i] = b_ih[i] + b_hh[i];
    if (tid < 256) { wposI[2 * tid] = W_pos[tid]; wposI[2 * tid + 1] = W_pos[HH + tid]; }
    for (int i = tid; i < 128; i += NT) { s_wun2[i] = W_un2[i]; s_wemb[i] = W_embed[i]; }
    if (tid < 64) {
        s_bsp1[tid] = b_sp1[tid]; s_bun1[tid] = b_un1[tid];
        s_wsp2[tid] = W_sp2[tid]; s_bemb[tid] = b_embed[tid];
    }
    if (tid == 0) {
        s_misc[0] = b_pos[0]; s_misc[1] = b_pos[1];
        s_misc[2] = b_sp2[0]; s_misc[3] = b_un2[0]; s_misc[4] = b_un2[1];
    }

    // c-state in registers: c2[hc*8+r] = pair (j=hc*64+2*lane, +1) of row myrow+r
    u64 c2[32];
    #pragma unroll
    for (int hc = 0; hc < 4; hc++)
        #pragma unroll
        for (int r = 0; r < 8; r++) {
            float2 v = *(const float2*)&enc_c[(size_t)(row0 + myrow + r) * HH + hc * 64 + 2 * lane];
            c2[hc * 8 + r] = pack2(v.x, v.y);
        }
    __syncthreads();

    float* out_pred = out;
    float* out_sp   = out + (size_t)BB * PP * 2;
    float* out_un   = out + (size_t)BB * PP * 3;

    for (int step = 0; step < PP; step++) {
        float* hsOld = (step & 1) ? hs1 : hs0;
        float* hsNew = (step & 1) ? hs0 : hs1;

        // ---- 1. emb (per-warp: own 8 rows only) ----
        for (int i = lane; i < 8 * EE; i += 32) {
            int r = i >> 6, e = i & 63;
            int row = myrow + r;
            float v = fmaf(ps[row * 2], s_wemb[e * 2],
                      fmaf(ps[row * 2 + 1], s_wemb[e * 2 + 1], s_bemb[e]));
            embs[row * EE + e] = fmaxf(v, 0.f);
        }
        __syncwarp();

        // ---- 2. gates GEMM (FFMA2) + fused LSTM cell, 4 output chunks ----
        #pragma unroll 1
        for (int hc = 0; hc < 4; hc++) {
            u64 acc2[32];  // [gate 4][row 8]
            #pragma unroll
            for (int i = 0; i < 32; i++) acc2[i] = 0ULL;

            for (int kt = 0; kt < KTOT; kt += KT) {
                __syncthreads();
                #pragma unroll
                for (int it = 0; it < 8; it++) {          // KT*256/4/NT = 8
                    int fi  = it * NT + tid;
                    int k   = fi >> 6;
                    int jl4 = fi & 63;
                    int g   = jl4 >> 4;
                    int jj  = (jl4 & 15) * 4;
                    *(float4*)&wt[k * 256 + jl4 * 4] =
                        *(const float4*)&g_Wt[(size_t)(kt + k) * G4 + g * 256 + hc * 64 + jj];
                }
                __syncthreads();

                const float* Abase = (kt < EE) ? (embs + kt) : (hsOld + (kt - EE));
                const int astr     = (kt < EE) ? EE : HH;

                for (int k4 = 0; k4 < KT; k4 += 4) {
                    float4 a[8];
                    #pragma unroll
                    for (int r = 0; r < 8; r++)
                        a[r] = *(const float4*)&Abase[(myrow + r) * astr + k4];
                    #pragma unroll
                    for (int kk = 0; kk < 4; kk++) {
                        const float* wr = &wt[(k4 + kk) * 256 + 2 * lane];
                        u64 w0 = *(const u64*)&wr[0];
                        u64 w1 = *(const u64*)&wr[64];
                        u64 w2 = *(const u64*)&wr[128];
                        u64 w3 = *(const u64*)&wr[192];
                        #pragma unroll
                        for (int r = 0; r < 8; r++) {
                            float av = (kk == 0) ? a[r].x : (kk == 1) ? a[r].y
                                     : (kk == 2) ? a[r].z : a[r].w;
                            u64 av2 = pack2(av, av);
                            FMA2(acc2[r],      av2, w0);
                            FMA2(acc2[8 + r],  av2, w1);
                            FMA2(acc2[16 + r], av2, w2);
                            FMA2(acc2[24 + r], av2, w3);
                        }
                    }
                }
            }
            // fused LSTM cell update; writes h straight into hsNew (own rows)
            int jb = hc * 64 + 2 * lane;
            float2 bi = *(const float2*)&bg[jb];
            float2 bf = *(const float2*)&bg[256 + jb];
            float2 bgt = *(const float2*)&bg[512 + jb];
            float2 bo = *(const float2*)&bg[768 + jb];
            #pragma unroll
            for (int r = 0; r < 8; r++) {
                float i0, i1, f0, f1, g0, g1, o0, o1, co0, co1;
                unpack2(acc2[r],      i0, i1);
                unpack2(acc2[8 + r],  f0, f1);
                unpack2(acc2[16 + r], g0, g1);
                unpack2(acc2[24 + r], o0, o1);
                unpack2(c2[hc * 8 + r], co0, co1);
                float cn0 = sigf(f0 + bf.x) * co0 + sigf(i0 + bi.x) * tanhf(g0 + bgt.x);
                float cn1 = sigf(f1 + bf.y) * co1 + sigf(i1 + bi.y) * tanhf(g1 + bgt.y);
                c2[hc * 8 + r] = pack2(cn0, cn1);
                float h0 = sigf(o0 + bo.x) * tanhf(cn0);
                float h1 = sigf(o1 + bo.y) * tanhf(cn1);
                *(float2*)&hsNew[(myrow + r) * HH + jb] = make_float2(h0, h1);
            }
        }

        // ---- 3. heads (packed pairs; reads hsNew, own rows only) ----
        u64 t2[8], u2[8], p2[8];
        #pragma unroll
        for (int r = 0; r < 8; r++) { t2[r] = 0ULL; u2[r] = 0ULL; p2[r] = 0ULL; }

        for (int kt = 0; kt < HH; kt += KTH) {
            __syncthreads();
            #pragma unroll
            for (int it = 0; it < 8; it++) {              // KTH*128/4/NT = 8
                int fi  = it * NT + tid;
                int k   = fi >> 5;
                int jl4 = fi & 31;
                *(float4*)&wt[k * 128 + jl4 * 4] =
                    *(const float4*)&g_WheadT[(kt + k) * 128 + jl4 * 4];
            }
            __syncthreads();
            for (int k = 0; k < KTH; k++) {
                const float* wr = &wt[k * 128];
                u64 wsp = *(const u64*)&wr[2 * lane];
                u64 wun = *(const u64*)&wr[64 + 2 * lane];
                u64 wpp = *(const u64*)&wposI[(kt + k) * 2];
                #pragma unroll
                for (int r = 0; r < 8; r++) {
                    float hv = hsNew[(myrow + r) * HH + kt + k];
                    u64 hv2 = pack2(hv, hv);
                    FMA2(t2[r], hv2, wsp);
                    FMA2(u2[r], hv2, wun);
                    FMA2(p2[r], hv2, wpp);
                }
            }
        }

        float bspa = s_bsp1[2 * lane], bspb = s_bsp1[2 * lane + 1];
        float buna = s_bun1[2 * lane], bunb = s_bun1[2 * lane + 1];
        float wspa = s_wsp2[2 * lane], wspb = s_wsp2[2 * lane + 1];
        float wu0a = s_wun2[2 * lane],      wu0b = s_wun2[2 * lane + 1];
        float wu1a = s_wun2[64 + 2 * lane], wu1b = s_wun2[64 + 2 * lane + 1];

        #pragma unroll
        for (int r = 0; r < 8; r++) {
            float ta, tb, ua, ub, pr0, pr1;
            unpack2(t2[r], ta, tb);
            unpack2(u2[r], ua, ub);
            unpack2(p2[r], pr0, pr1);
            ta = fmaxf(ta + bspa, 0.f); tb = fmaxf(tb + bspb, 0.f);
            ua = fmaxf(ua + buna, 0.f); ub = fmaxf(ub + bunb, 0.f);
            float spv = ta * wspa + tb * wspb;
            float un0 = ua * wu0a + ub * wu0b;
            float un1 = ua * wu1a + ub * wu1b;
            #pragma unroll
            for (int off = 16; off > 0; off >>= 1) {
                spv += __shfl_xor_sync(0xffffffffu, spv, off);
                un0 += __shfl_xor_sync(0xffffffffu, un0, off);
                un1 += __shfl_xor_sync(0xffffffffu, un1, off);
            }
            if (lane == 0) {
                int row = myrow + r;
                int b   = row0 + row;
                float p0 = ps[row * 2]     + pr0 + s_misc[0];
                float p1 = ps[row * 2 + 1] + pr1 + s_misc[1];
                size_t base = (size_t)b * PP + step;
                out_pred[base * 2]     = p0;
                out_pred[base * 2 + 1] = p1;
                out_sp[base]           = softplusf(spv + s_misc[2]);
                out_un[base * 2]       = expf(un0 + s_misc[3]);
                out_un[base * 2 + 1]   = expf(un1 + s_misc[4]);
                ps[row * 2] = p0; ps[row * 2 + 1] = p1;
            }
        }
        __syncwarp();
    }
}

extern "C" void kernel_launch(void* const* d_in, const int* in_sizes, int n_in,
                              void* d_out, int out_size) {
    (void)in_sizes; (void)n_in; (void)out_size;
    const float* enc_h    = (const float*)d_in[0];
    const float* enc_c    = (const float*)d_in[1];
    const float* last_pos = (const float*)d_in[2];
    const float* W_embed  = (const float*)d_in[3];
    const float* b_embed  = (const float*)d_in[4];
    const float* W_ih     = (const float*)d_in[5];
    const float* W_hh     = (const float*)d_in[6];
    const float* b_ih     = (const float*)d_in[7];
    const float* b_hh     = (const float*)d_in[8];
    const float* W_pos    = (const float*)d_in[9];
    const float* b_pos    = (const float*)d_in[10];
    const float* W_sp1    = (const float*)d_in[11];
    const float* b_sp1    = (const float*)d_in[12];
    const float* W_sp2    = (const float*)d_in[13];
    const float* b_sp2    = (const float*)d_in[14];
    const float* W_un1    = (const float*)d_in[15];
    const float* b_un1    = (const float*)d_in[16];
    const float* W_un2    = (const float*)d_in[17];
    const float* b_un2    = (const float*)d_in[18];

    int prep_total = KTOT * G4 + HH * 128;
    prep_kernel<<<(prep_total + NT - 1) / NT, NT>>>(W_ih, W_hh, W_sp1, W_un1);

    const size_t smem = 47240 * sizeof(float);  // ~189 KB
    cudaFuncSetAttribute(lstm_kernel, cudaFuncAttributeMaxDynamicSharedMemorySize, (int)smem);
    lstm_kernel<<<BB / TM, NT, smem>>>(enc_h, enc_c, last_pos, W_embed, b_embed,
                                       b_ih, b_hh, W_pos, b_pos, b_sp1, W_sp2, b_sp2,
                                       b_un1, W_un2, b_un2, (float*)d_out);
}

// round 7
// speedup vs baseline: 1.1140x; 1.0553x over previous
#include <cuda_runtime.h>
#include <math.h>

#define BB 65536
#define HH 256
#define EE 64
#define DD 2
#define PP 12
#define G4 1024          // 4*H
#define KTOT 320         // E + H
#define TM 64            // rows per CTA
#define KT 32            // k-tile (gates)
#define KTH 64           // k-tile (heads)
#define NT 512           // threads per CTA (16 warps, 4 rows/warp)
#define NGT 40           // gate tiles: 4 hc * 10 ktiles
#define NTILES 44        // + 4 head tiles
#define SMEM_FLOATS 55456

typedef unsigned long long u64;

// -------- scratch (allocation-free: __device__ globals) --------
__device__ float g_Wt[KTOT * G4];      // packed transposed [k][g*256 + j]
__device__ float g_WheadT[HH * 128];   // [k][0..63]=W_sp1^T, [64..127]=W_un1^T

__global__ void prep_kernel(const float* __restrict__ W_ih,
                            const float* __restrict__ W_hh,
                            const float* __restrict__ W_sp1,
                            const float* __restrict__ W_un1) {
    int idx = blockIdx.x * blockDim.x + threadIdx.x;
    if (idx < KTOT * G4) {
        int k = idx >> 10, j = idx & 1023;
        g_Wt[idx] = (k < EE) ? W_ih[j * EE + k] : W_hh[j * HH + (k - EE)];
    } else {
        int r = idx - KTOT * G4;
        if (r < HH * 128) {
            int k = r >> 7, o = r & 127;
            g_WheadT[r] = (o < 64) ? W_sp1[o * HH + k] : W_un1[(o - 64) * HH + k];
        }
    }
}

__device__ __forceinline__ float sigf(float x) { return 1.f / (1.f + expf(-x)); }
__device__ __forceinline__ float softplusf(float x) {
    return fmaxf(x, 0.f) + log1pf(expf(-fabsf(x)));
}

__device__ __forceinline__ u64 pack2(float lo, float hi) {
    u64 r;
    asm("mov.b64 %0, {%1, %2};" : "=l"(r)
        : "r"(__float_as_uint(lo)), "r"(__float_as_uint(hi)));
    return r;
}
__device__ __forceinline__ void unpack2(u64 v, float& lo, float& hi) {
    unsigned int a, b;
    asm("mov.b64 {%0, %1}, %2;" : "=r"(a), "=r"(b) : "l"(v));
    lo = __uint_as_float(a); hi = __uint_as_float(b);
}
#define FMA2(d, a, b) asm("fma.rn.f32x2 %0, %1, %2, %0;" : "+l"(d) : "l"(a), "l"(b))

// -------- main persistent-state kernel --------
__global__ void __launch_bounds__(NT, 1)
lstm_kernel(const float* __restrict__ enc_h, const float* __restrict__ enc_c,
            const float* __restrict__ last_pos,
            const float* __restrict__ W_embed, const float* __restrict__ b_embed,
            const float* __restrict__ b_ih, const float* __restrict__ b_hh,
            const float* __restrict__ W_pos, const float* __restrict__ b_pos,
            const float* __restrict__ b_sp1, const float* __restrict__ W_sp2,
            const float* __restrict__ b_sp2,
            const float* __restrict__ b_un1, const float* __restrict__ W_un2,
            const float* __restrict__ b_un2,
            float* __restrict__ out)
{
    extern __shared__ float sm[];
    float* hs0   = sm;                    // [TM][HH] 16384
    float* hs1   = hs0 + TM * HH;         // [TM][HH] 16384
    float* embs  = hs1 + TM * HH;         // [TM][EE]  4096
    float* wtb   = embs + TM * EE;        // 2 x 8192 double-buffered tiles
    float* bg    = wtb + 2 * 8192;        // [1024]                (53248)
    float* wposI = bg + G4;               // [256][2] interleaved  (54272) 512
    float* s_bsp1 = wposI + 512;          // (54784) 64
    float* s_bun1 = s_bsp1 + 64;          // (54848) 64
    float* s_wsp2 = s_bun1 + 64;          // (54912) 64
    float* s_wun2 = s_wsp2 + 64;          // (54976) 128
    float* s_wemb = s_wun2 + 128;         // (55104) 128
    float* s_bemb = s_wemb + 128;         // (55232) 64
    float* s_misc = s_bemb + 64;          // (55296) 8
    float* ps     = s_misc + 8;           // (55304) 128  -> end 55432 <= SMEM_FLOATS

    const int tid  = threadIdx.x;
    const int lane = tid & 31;
    const int w    = tid >> 5;            // 0..15
    const int row0 = blockIdx.x * TM;
    const int myrow = w * 4;              // warp owns 4 rows

    // ---- init ----
    for (int i = tid; i < TM * HH; i += NT) hs0[i] = enc_h[row0 * HH + i];
    for (int i = tid; i < TM * DD; i += NT) ps[i] = last_pos[row0 * DD + i];
    for (int i = tid; i < G4; i += NT) bg[i] = b_ih[i] + b_hh[i];
    if (tid < 256) { wposI[2 * tid] = W_pos[tid]; wposI[2 * tid + 1] = W_pos[HH + tid]; }
    for (int i = tid; i < 128; i += NT) { s_wun2[i] = W_un2[i]; s_wemb[i] = W_embed[i]; }
    if (tid < 64) {
        s_bsp1[tid] = b_sp1[tid]; s_bun1[tid] = b_un1[tid];
        s_wsp2[tid] = W_sp2[tid]; s_bemb[tid] = b_embed[tid];
    }
    if (tid == 0) {
        s_misc[0] = b_pos[0]; s_misc[1] = b_pos[1];
        s_misc[2] = b_sp2[0]; s_misc[3] = b_un2[0]; s_misc[4] = b_un2[1];
    }

    // c-state in registers: c2[hc*4+r] = pair (j=hc*64+2*lane, +1) of row myrow+r
    u64 c2[16];
    #pragma unroll
    for (int hc = 0; hc < 4; hc++)
        #pragma unroll
        for (int r = 0; r < 4; r++) {
            float2 v = *(const float2*)&enc_c[(size_t)(row0 + myrow + r) * HH + hc * 64 + 2 * lane];
            c2[hc * 4 + r] = pack2(v.x, v.y);
        }
    __syncthreads();

    float* out_pred = out;
    float* out_sp   = out + (size_t)BB * PP * 2;
    float* out_un   = out + (size_t)BB * PP * 3;

    for (int step = 0; step < PP; step++) {
        float* hsOld = (step & 1) ? hs1 : hs0;
        float* hsNew = (step & 1) ? hs0 : hs1;

        // ---- 1. emb (per-warp: own 4 rows only) ----
        for (int i = lane; i < 4 * EE; i += 32) {
            int r = i >> 6, e = i & 63;
            int row = myrow + r;
            float v = fmaf(ps[row * 2], s_wemb[e * 2],
                      fmaf(ps[row * 2 + 1], s_wemb[e * 2 + 1], s_bemb[e]));
            embs[row * EE + e] = fmaxf(v, 0.f);
        }
        __syncwarp();

        // ---- staging helper (inline): tile t -> buffer ----
        #define STAGE(t)  do {                                                      \
            float* dst = wtb + ((t) & 1) * 8192;                                    \
            if ((t) < NGT) {                                                        \
                int hc_ = (t) / 10, kt_ = ((t) % 10) * KT;                          \
                _Pragma("unroll")                                                   \
                for (int it = 0; it < 4; it++) {                                    \
                    int fi  = it * NT + tid;                                        \
                    int k   = fi >> 6;                                              \
                    int jl4 = fi & 63;                                              \
                    int g   = jl4 >> 4;                                             \
                    int jj  = (jl4 & 15) * 4;                                       \
                    *(float4*)&dst[k * 256 + jl4 * 4] =                             \
                        *(const float4*)&g_Wt[(size_t)(kt_ + k) * G4 + g * 256 + hc_ * 64 + jj]; \
                }                                                                   \
            } else {                                                                \
                int kt_ = ((t) - NGT) * KTH;                                        \
                _Pragma("unroll")                                                   \
                for (int it = 0; it < 4; it++) {                                    \
                    int fi  = it * NT + tid;                                        \
                    int k   = fi >> 5;                                              \
                    int jl4 = fi & 31;                                              \
                    *(float4*)&dst[k * 128 + jl4 * 4] =                             \
                        *(const float4*)&g_WheadT[(kt_ + k) * 128 + jl4 * 4];       \
                }                                                                   \
            }                                                                       \
        } while (0)

        STAGE(0);
        __syncthreads();

        // ---- 2. gates GEMM (FFMA2) + fused LSTM cell, 4 output chunks ----
        #pragma unroll 1
        for (int hc = 0; hc < 4; hc++) {
            u64 acc2[16];  // [gate 4][row 4]
            #pragma unroll
            for (int i = 0; i < 16; i++) acc2[i] = 0ULL;

            #pragma unroll 1
            for (int ti = 0; ti < 10; ti++) {
                int t = hc * 10 + ti;
                if (t + 1 < NTILES) STAGE(t + 1);
                const float* wt = wtb + (t & 1) * 8192;

                int kt = ti * KT;
                const float* Abase = (kt < EE) ? (embs + kt) : (hsOld + (kt - EE));
                const int astr     = (kt < EE) ? EE : HH;

                for (int k4 = 0; k4 < KT; k4 += 4) {
                    float4 a[4];
                    #pragma unroll
                    for (int r = 0; r < 4; r++)
                        a[r] = *(const float4*)&Abase[(myrow + r) * astr + k4];
                    #pragma unroll
                    for (int kk = 0; kk < 4; kk++) {
                        const float* wr = &wt[(k4 + kk) * 256 + 2 * lane];
                        u64 w0 = *(const u64*)&wr[0];
                        u64 w1 = *(const u64*)&wr[64];
                        u64 w2 = *(const u64*)&wr[128];
                        u64 w3 = *(const u64*)&wr[192];
                        #pragma unroll
                        for (int r = 0; r < 4; r++) {
                            float av = (kk == 0) ? a[r].x : (kk == 1) ? a[r].y
                                     : (kk == 2) ? a[r].z : a[r].w;
                            u64 av2 = pack2(av, av);
                            FMA2(acc2[r],      av2, w0);
                            FMA2(acc2[4 + r],  av2, w1);
                            FMA2(acc2[8 + r],  av2, w2);
                            FMA2(acc2[12 + r], av2, w3);
                        }
                    }
                }
                __syncthreads();
            }
            // fused LSTM cell update; writes h straight into hsNew (own rows)
            int jb = hc * 64 + 2 * lane;
            float2 bi = *(const float2*)&bg[jb];
            float2 bf = *(const float2*)&bg[256 + jb];
            float2 bgt = *(const float2*)&bg[512 + jb];
            float2 bo = *(const float2*)&bg[768 + jb];
            #pragma unroll
            for (int r = 0; r < 4; r++) {
                float i0, i1, f0, f1, g0, g1, o0, o1, co0, co1;
                unpack2(acc2[r],      i0, i1);
                unpack2(acc2[4 + r],  f0, f1);
                unpack2(acc2[8 + r],  g0, g1);
                unpack2(acc2[12 + r], o0, o1);
                unpack2(c2[hc * 4 + r], co0, co1);
                float cn0 = sigf(f0 + bf.x) * co0 + sigf(i0 + bi.x) * tanhf(g0 + bgt.x);
                float cn1 = sigf(f1 + bf.y) * co1 + sigf(i1 + bi.y) * tanhf(g1 + bgt.y);
                c2[hc * 4 + r] = pack2(cn0, cn1);
                float h0 = sigf(o0 + bo.x) * tanhf(cn0);
                float h1 = sigf(o1 + bo.y) * tanhf(cn1);
                *(float2*)&hsNew[(myrow + r) * HH + jb] = make_float2(h0, h1);
            }
        }
        __syncwarp();   // hsNew (own rows) visible across lanes before heads read

        // ---- 3. heads (packed pairs; reads hsNew, own rows only) ----
        u64 t2[4], u2[4], p2[4];
        #pragma unroll
        for (int r = 0; r < 4; r++) { t2[r] = 0ULL; u2[r] = 0ULL; p2[r] = 0ULL; }

        #pragma unroll 1
        for (int ht = 0; ht < 4; ht++) {
            int t = NGT + ht;
            if (t + 1 < NTILES) STAGE(t + 1);
            const float* wt = wtb + (t & 1) * 8192;
            int kt = ht * KTH;
            for (int k = 0; k < KTH; k++) {
                const float* wr = &wt[k * 128];
                u64 wsp = *(const u64*)&wr[2 * lane];
                u64 wun = *(const u64*)&wr[64 + 2 * lane];
                u64 wpp = *(const u64*)&wposI[(kt + k) * 2];
                #pragma unroll
                for (int r = 0; r < 4; r++) {
                    float hv = hsNew[(myrow + r) * HH + kt + k];
                    u64 hv2 = pack2(hv, hv);
                    FMA2(t2[r], hv2, wsp);
                    FMA2(u2[r], hv2, wun);
                    FMA2(p2[r], hv2, wpp);
                }
            }
            __syncthreads();
        }

        float bspa = s_bsp1[2 * lane], bspb = s_bsp1[2 * lane + 1];
        float buna = s_bun1[2 * lane], bunb = s_bun1[2 * lane + 1];
        float wspa = s_wsp2[2 * lane], wspb = s_wsp2[2 * lane + 1];
        float wu0a = s_wun2[2 * lane],      wu0b = s_wun2[2 * lane + 1];
        float wu1a = s_wun2[64 + 2 * lane], wu1b = s_wun2[64 + 2 * lane + 1];

        #pragma unroll
        for (int r = 0; r < 4; r++) {
            float ta, tb, ua, ub, pr0, pr1;
            unpack2(t2[r], ta, tb);
            unpack2(u2[r], ua, ub);
            unpack2(p2[r], pr0, pr1);
            ta = fmaxf(ta + bspa, 0.f); tb = fmaxf(tb + bspb, 0.f);
            ua = fmaxf(ua + buna, 0.f); ub = fmaxf(ub + bunb, 0.f);
            float spv = ta * wspa + tb * wspb;
            float un0 = ua * wu0a + ub * wu0b;
            float un1 = ua * wu1a + ub * wu1b;
            #pragma unroll
            for (int off = 16; off > 0; off >>= 1) {
                spv += __shfl_xor_sync(0xffffffffu, spv, off);
                un0 += __shfl_xor_sync(0xffffffffu, un0, off);
                un1 += __shfl_xor_sync(0xffffffffu, un1, off);
            }
            if (lane == 0) {
                int row = myrow + r;
                int b   = row0 + row;
                float p0 = ps[row * 2]     + pr0 + s_misc[0];
                float p1 = ps[row * 2 + 1] + pr1 + s_misc[1];
                size_t base = (size_t)b * PP + step;
                out_pred[base * 2]     = p0;
                out_pred[base * 2 + 1] = p1;
                out_sp[base]           = softplusf(spv + s_misc[2]);
                out_un[base * 2]       = expf(un0 + s_misc[3]);
                out_un[base * 2 + 1]   = expf(un1 + s_misc[4]);
                ps[row * 2] = p0; ps[row * 2 + 1] = p1;
            }
        }
        __syncwarp();
        #undef STAGE
    }
}

extern "C" void kernel_launch(void* const* d_in, const int* in_sizes, int n_in,
                              void* d_out, int out_size) {
    (void)in_sizes; (void)n_in; (void)out_size;
    const float* enc_h    = (const float*)d_in[0];
    const float* enc_c    = (const float*)d_in[1];
    const float* last_pos = (const float*)d_in[2];
    const float* W_embed  = (const float*)d_in[3];
    const float* b_embed  = (const float*)d_in[4];
    const float* W_ih     = (const float*)d_in[5];
    const float* W_hh     = (const float*)d_in[6];
    const float* b_ih     = (const float*)d_in[7];
    const float* b_hh     = (const float*)d_in[8];
    const float* W_pos    = (const float*)d_in[9];
    const float* b_pos    = (const float*)d_in[10];
    const float* W_sp1    = (const float*)d_in[11];
    const float* b_sp1    = (const float*)d_in[12];
    const float* W_sp2    = (const float*)d_in[13];
    const float* b_sp2    = (const float*)d_in[14];
    const float* W_un1    = (const float*)d_in[15];
    const float* b_un1    = (const float*)d_in[16];
    const float* W_un2    = (const float*)d_in[17];
    const float* b_un2    = (const float*)d_in[18];

    int prep_total = KTOT * G4 + HH * 128;
    prep_kernel<<<(prep_total + 255) / 256, 256>>>(W_ih, W_hh, W_sp1, W_un1);

    const size_t smem = SMEM_FLOATS * sizeof(float);  // ~216.6 KB
    cudaFuncSetAttribute(lstm_kernel, cudaFuncAttributeMaxDynamicSharedMemorySize, (int)smem);
    lstm_kernel<<<BB / TM, NT, smem>>>(enc_h, enc_c, last_pos, W_embed, b_embed,
                                       b_ih, b_hh, W_pos, b_pos, b_sp1, W_sp2, b_sp2,
                                       b_un1, W_un2, b_un2, (float*)d_out);
}